// round 15
// baseline (speedup 1.0000x reference)
#include <cuda_runtime.h>
#include <math.h>
#include <stdint.h>

#define TDIM 4096
#define MDIM 512
#define DDIM 64
#define WPAD 68
#define XSTR 40
#define BSTR 516
#define TILE 32
#define NTHR 256
#define NSM  152
#define LN_M 6.2383246250395075f

#define OFF_W   0                       // W tf32 [512][68] = 34816 words
#define OFF_X   34816                   // X tf32 [64][40]  = 2560
#define OFF_BUF 37376                   // buf [32][516]    = 16512
#define SMEM_FLOATS (OFF_BUF + 16512)

__device__ float g_avg[MDIM];
__device__ float g_kl;

static __device__ __forceinline__ uint32_t f2tf32(float v) {
    uint32_t b; asm("cvt.rna.tf32.f32 %0, %1;" : "=r"(b) : "f"(v)); return b;
}
static __device__ __forceinline__ void mma8(float d[4], uint32_t a0, uint32_t a1,
                                            uint32_t a2, uint32_t a3,
                                            uint32_t b0, uint32_t b1) {
    asm volatile("mma.sync.aligned.m16n8k8.row.col.f32.tf32.tf32.f32 "
                 "{%0,%1,%2,%3},{%4,%5,%6,%7},{%8,%9},{%0,%1,%2,%3};"
                 : "+f"(d[0]), "+f"(d[1]), "+f"(d[2]), "+f"(d[3])
                 : "r"(a0), "r"(a1), "r"(a2), "r"(a3), "r"(b0), "r"(b1));
}
// log(u), u in [1e-9,1): MUFU away from 1, 3-term Taylor near 1 (validated)
static __device__ __forceinline__ float log_u(float uu) {
    const float t = uu - 1.0f;
    const float near1 = t * fmaf(t, fmaf(t, 0.33333333f, -0.5f), 1.0f);
    return (uu > 0.999f) ? near1 : __logf(uu);
}
static __device__ __forceinline__ float warp_sum(float v) {
#pragma unroll
    for (int m = 16; m > 0; m >>= 1) v += __shfl_xor_sync(0xffffffffu, v, m);
    return v;
}

__global__ void vq_zero_kernel() {
    if (threadIdx.x < MDIM) g_avg[threadIdx.x] = 0.f;
    if (threadIdx.x == 0) g_kl = 0.f;
}

__global__ void __launch_bounds__(NTHR, 1)
vq_main_kernel(const float* __restrict__ x, const float* __restrict__ u,
               const float* __restrict__ w, float* __restrict__ out, int n_tiles)
{
    extern __shared__ float sm[];
    uint32_t* wtu = (uint32_t*)(sm + OFF_W);     // tf32 W, [m][WPAD]
    uint32_t* xsu = (uint32_t*)(sm + OFF_X);     // tf32 X, [d][XSTR]
    float*    buf = sm + OFF_BUF;                // logits then tf32 samples
    uint32_t* bufu = (uint32_t*)buf;

    const int tid = threadIdx.x, lane = tid & 31, warp = tid >> 5;
    const int r0 = warp * 4;
    const int g = lane >> 2, tig = lane & 3;
    const int mbase = warp * 64;

    // ---- stage W once as tf32 (rounded: unbiased) ----
    for (int i = tid; i < MDIM * DDIM; i += NTHR)
        wtu[(i >> 6) * WPAD + (i & 63)] = f2tf32(w[i]);
    __syncthreads();
    // ---- wsq from the tf32 codebook (consistent with both GEMMs) ----
    for (int m = tid; m < MDIM; m += NTHR) {
        float acc = 0.f;
#pragma unroll
        for (int d = 0; d < DDIM; d += 4) {
            const uint4 q = *(const uint4*)&wtu[m * WPAD + d];
            const float v0 = __uint_as_float(q.x), v1 = __uint_as_float(q.y);
            const float v2 = __uint_as_float(q.z), v3 = __uint_as_float(q.w);
            acc += v0 * v0 + v1 * v1 + v2 * v2 + v3 * v3;
        }
        buf[m] = acc;
    }
    __syncthreads();
    float wsql[16];
#pragma unroll
    for (int j = 0; j < 16; j++) wsql[j] = buf[j * 32 + lane];

    float avg_acc[16];
#pragma unroll
    for (int j = 0; j < 16; j++) avg_acc[j] = 0.f;
    float kl_acc = 0.f;          // row-scalar accumulator (lane-uniform)

    for (int tile = blockIdx.x; tile < n_tiles; tile += gridDim.x) {
        const int b  = tile >> 7;
        const int t0 = (tile & 127) * TILE;

        __syncthreads();                        // prev tile fully consumed
        for (int i = tid; i < DDIM * TILE; i += NTHR) {
            const int d = i >> 5, t = i & 31;
            xsu[d * XSTR + t] = f2tf32(2.0f * x[((size_t)b * DDIM + d) * TDIM + t0 + t]);
        }
        __syncthreads();

        // ========== GEMM1 (mma.sync tf32): D[m][t] = w_m . 2x_t ==========
        uint32_t bf[4][16];
#pragma unroll
        for (int nt = 0; nt < 4; nt++)
#pragma unroll
            for (int k = 0; k < 8; k++) {
                bf[nt][k*2]   = xsu[(k*8 + tig)     * XSTR + nt*8 + g];
                bf[nt][k*2+1] = xsu[(k*8 + tig + 4) * XSTR + nt*8 + g];
            }
        float dre[4][4][4];
#pragma unroll
        for (int mt = 0; mt < 4; mt++)
#pragma unroll
            for (int nt = 0; nt < 4; nt++)
#pragma unroll
                for (int i = 0; i < 4; i++) dre[mt][nt][i] = 0.f;
#pragma unroll
        for (int mt = 0; mt < 4; mt++) {
            const uint32_t* wr0 = wtu + (mbase + mt*16 + g) * WPAD;
            const uint32_t* wr1 = wr0 + 8 * WPAD;
#pragma unroll
            for (int k = 0; k < 8; k++) {
                const uint32_t a0 = wr0[k*8 + tig];
                const uint32_t a1 = wr1[k*8 + tig];
                const uint32_t a2 = wr0[k*8 + tig + 4];
                const uint32_t a3 = wr1[k*8 + tig + 4];
#pragma unroll
                for (int nt = 0; nt < 4; nt++)
                    mma8(dre[mt][nt], a0, a1, a2, a3, bf[nt][k*2], bf[nt][k*2+1]);
            }
        }
#pragma unroll
        for (int mt = 0; mt < 4; mt++)
#pragma unroll
            for (int nt = 0; nt < 4; nt++) {
                const int tcol = nt*8 + 2*tig;
                const int m0 = mbase + mt*16 + g;
                buf[tcol * BSTR + m0]           = dre[mt][nt][0];
                buf[(tcol + 1) * BSTR + m0]     = dre[mt][nt][1];
                buf[tcol * BSTR + m0 + 8]       = dre[mt][nt][2];
                buf[(tcol + 1) * BSTR + m0 + 8] = dre[mt][nt][3];
            }

        // Prefetch ALL u for this warp's 4 rows (MLP=64) before the barrier.
        float uu[4][16];
        {
            const float* ub = u + (size_t)(b * TDIM + t0 + r0) * MDIM + lane;
#pragma unroll
            for (int r = 0; r < 4; r++)
#pragma unroll
                for (int j = 0; j < 16; j++)
                    uu[r][j] = ub[(size_t)r * MDIM + j*32];
        }
        __syncthreads();

        // ========== fused softmax pass ==========
        // s bounded (|s| < ~1, weights ~ U(+-1/512)) -> exp(s) needs no max shift.
        // KL row = ses/se - log(se) + lnM   (exact identity)
        // gumbel sample weight: val = (e / log(u))^2 = exp(2s) * exp(2*gumbel)
        float s[4][16];
#pragma unroll
        for (int r = 0; r < 4; r++)
#pragma unroll
            for (int j = 0; j < 16; j++)
                s[r][j] = buf[(r0 + r) * BSTR + j*32 + lane] - wsql[j];

        float se[4]  = {0.f, 0.f, 0.f, 0.f};
        float ses[4] = {0.f, 0.f, 0.f, 0.f};
        float sy[4]  = {0.f, 0.f, 0.f, 0.f};
#pragma unroll
        for (int r = 0; r < 4; r++)
#pragma unroll
            for (int j = 0; j < 16; j++) {
                const float sv = s[r][j];
                const float e  = __expf(sv);
                se[r]  += e;
                ses[r] += e * sv;
                const float v = fminf(fmaxf(uu[r][j], 1e-9f), 0.99999994f);
                const float t = __fdividef(e, log_u(v));   // e / log(u)  (negative)
                const float val = t * t;                   // squared: positive
                s[r][j] = val;
                sy[r]  += val;
            }
        // one batched butterfly for all 12 row-scalars
#pragma unroll
        for (int m = 16; m > 0; m >>= 1)
#pragma unroll
            for (int r = 0; r < 4; r++) {
                se[r]  += __shfl_xor_sync(0xffffffffu, se[r],  m);
                ses[r] += __shfl_xor_sync(0xffffffffu, ses[r], m);
                sy[r]  += __shfl_xor_sync(0xffffffffu, sy[r],  m);
            }
#pragma unroll
        for (int r = 0; r < 4; r++) {
            const float lse = logf(se[r]);   // precise (MUFU bias breaks KL)
            kl_acc += __fdividef(ses[r], se[r]) - lse + LN_M;
            const float inv = 1.0f / sy[r];
#pragma unroll
            for (int j = 0; j < 16; j++) {
                const float p = s[r][j] * inv;
                avg_acc[j] += p;
                bufu[(r0 + r) * BSTR + j*32 + lane] = f2tf32(p);
            }
        }
        __syncthreads();

        // ========== GEMM2 (mma.sync tf32): out[t][d] = p . w ==========
        {
            const int tt0 = (warp & 1) * 16;
            const int dt0 = (warp >> 1) * 16;
            float dacc[2][4];
#pragma unroll
            for (int nt = 0; nt < 2; nt++)
#pragma unroll
                for (int i = 0; i < 4; i++) dacc[nt][i] = 0.f;
#pragma unroll 8
            for (int k0 = 0; k0 < MDIM; k0 += 8) {
                const uint32_t a0 = bufu[(tt0 + g)     * BSTR + k0 + tig];
                const uint32_t a1 = bufu[(tt0 + g + 8) * BSTR + k0 + tig];
                const uint32_t a2 = bufu[(tt0 + g)     * BSTR + k0 + tig + 4];
                const uint32_t a3 = bufu[(tt0 + g + 8) * BSTR + k0 + tig + 4];
#pragma unroll
                for (int nt = 0; nt < 2; nt++) {
                    const uint32_t b0 = wtu[(k0 + tig)     * WPAD + dt0 + nt*8 + g];
                    const uint32_t b1 = wtu[(k0 + tig + 4) * WPAD + dt0 + nt*8 + g];
                    mma8(dacc[nt], a0, a1, a2, a3, b0, b1);
                }
            }
            float* ob = out + (size_t)(b * TDIM + t0 + tt0) * DDIM;
#pragma unroll
            for (int nt = 0; nt < 2; nt++) {
                const int d0 = dt0 + nt*8 + 2*tig;
                *(float2*)&ob[(size_t)g * DDIM + d0]       = make_float2(dacc[nt][0], dacc[nt][1]);
                *(float2*)&ob[(size_t)(g + 8) * DDIM + d0] = make_float2(dacc[nt][2], dacc[nt][3]);
            }
        }
    }

    // ---- epilogue: CTA reduce in buf, then global atomics ----
    __syncthreads();
    for (int i = tid; i < MDIM; i += NTHR) buf[i] = 0.f;
    __syncthreads();
#pragma unroll
    for (int j = 0; j < 16; j++) atomicAdd(&buf[j*32 + lane], avg_acc[j]);
    __syncthreads();
    for (int i = tid; i < MDIM; i += NTHR) atomicAdd(&g_avg[i], buf[i]);
    // kl_acc is lane-uniform (built from reduced row scalars): one lane adds it
    if (lane == 0) atomicAdd(&g_kl, kl_acc);
}

__global__ void vq_finalize_kernel(float* __restrict__ out, long long q, int B,
                                   float invN, long long out_size)
{
    __shared__ float red[16];
    const int tid = threadIdx.x, lane = tid & 31, warp = tid >> 5;
    const float a = g_avg[tid] * invN;
    float v = a * logf(a + 1e-10f);
    v = warp_sum(v);
    if (lane == 0) red[warp] = v;
    __syncthreads();
    if (tid == 0) {
        float t = 0.f;
#pragma unroll
        for (int i = 0; i < 16; i++) t += red[i];
        if (q < out_size)     out[q]     = g_kl / (float)B;
        if (q + 1 < out_size) out[q + 1] = expf(-t);
    }
}

extern "C" void kernel_launch(void* const* d_in, const int* in_sizes, int n_in,
                              void* d_out, int out_size)
{
    const float* x = (const float*)d_in[0];
    const float* u = (const float*)d_in[1];
    const float* w = (const float*)d_in[2];
    float* out = (float*)d_out;

    const int B = in_sizes[0] / (DDIM * TDIM);
    const int n_tiles = B * (TDIM / TILE);
    const long long q = (long long)B * TDIM * DDIM;

    const size_t smem_bytes = SMEM_FLOATS * sizeof(float);
    cudaFuncSetAttribute(vq_main_kernel,
                         cudaFuncAttributeMaxDynamicSharedMemorySize, (int)smem_bytes);
    const int grid = (n_tiles < NSM) ? n_tiles : NSM;

    vq_zero_kernel<<<1, 512>>>();
    vq_main_kernel<<<grid, NTHR, smem_bytes>>>(x, u, w, out, n_tiles);
    vq_finalize_kernel<<<1, 512>>>(out, q, B,
                                   1.0f / (float)((long long)B * TDIM),
                                   (long long)out_size);
    vq_zero_kernel<<<1, 512>>>();
}

// round 16
// speedup vs baseline: 1.1547x; 1.1547x over previous
#include <cuda_runtime.h>
#include <math.h>
#include <stdint.h>

#define TDIM 4096
#define MDIM 512
#define DDIM 64
#define WPAD 68
#define XSTR 40
#define BSTR 516
#define TILE 32
#define NTHR 256
#define NSM  152
#define LN_M 6.2383246250395075f

#define OFF_W   0                       // W tf32 [512][68] = 34816 words
#define OFF_X   34816                   // X tf32 [64][40]  = 2560
#define OFF_BUF 37376                   // buf [32][516]    = 16512
#define SMEM_FLOATS (OFF_BUF + 16512)

__device__ float g_avg[MDIM];
__device__ float g_kl;

static __device__ __forceinline__ uint32_t f2tf32(float v) {
    uint32_t b; asm("cvt.rna.tf32.f32 %0, %1;" : "=r"(b) : "f"(v)); return b;
}
static __device__ __forceinline__ void mma8(float d[4], uint32_t a0, uint32_t a1,
                                            uint32_t a2, uint32_t a3,
                                            uint32_t b0, uint32_t b1) {
    asm volatile("mma.sync.aligned.m16n8k8.row.col.f32.tf32.tf32.f32 "
                 "{%0,%1,%2,%3},{%4,%5,%6,%7},{%8,%9},{%0,%1,%2,%3};"
                 : "+f"(d[0]), "+f"(d[1]), "+f"(d[2]), "+f"(d[3])
                 : "r"(a0), "r"(a1), "r"(a2), "r"(a3), "r"(b0), "r"(b1));
}
// log(u), u in [1e-9,1): MUFU away from 1, 3-term Taylor near 1 (validated)
static __device__ __forceinline__ float log_u(float uu) {
    const float t = uu - 1.0f;
    const float near1 = t * fmaf(t, fmaf(t, 0.33333333f, -0.5f), 1.0f);
    return (uu > 0.999f) ? near1 : __logf(uu);
}
static __device__ __forceinline__ float warp_sum(float v) {
#pragma unroll
    for (int m = 16; m > 0; m >>= 1) v += __shfl_xor_sync(0xffffffffu, v, m);
    return v;
}

__global__ void vq_zero_kernel() {
    if (threadIdx.x < MDIM) g_avg[threadIdx.x] = 0.f;
    if (threadIdx.x == 0) g_kl = 0.f;
}

__global__ void __launch_bounds__(NTHR, 1)
vq_main_kernel(const float* __restrict__ x, const float* __restrict__ u,
               const float* __restrict__ w, float* __restrict__ out, int n_tiles)
{
    extern __shared__ float sm[];
    uint32_t* wtu = (uint32_t*)(sm + OFF_W);     // tf32 W, [m][WPAD]
    uint32_t* xsu = (uint32_t*)(sm + OFF_X);     // tf32 X, [d][XSTR]
    float*    buf = sm + OFF_BUF;                // logits then tf32 samples
    uint32_t* bufu = (uint32_t*)buf;

    const int tid = threadIdx.x, lane = tid & 31, warp = tid >> 5;
    const int r0 = warp * 4;
    const int g = lane >> 2, tig = lane & 3;
    const int mbase = warp * 64;

    // ---- stage W once as tf32 (rounded: unbiased) ----
    for (int i = tid; i < MDIM * DDIM; i += NTHR)
        wtu[(i >> 6) * WPAD + (i & 63)] = f2tf32(w[i]);
    __syncthreads();
    // ---- wsq from the tf32 codebook (consistent with both GEMMs) ----
    for (int m = tid; m < MDIM; m += NTHR) {
        float acc = 0.f;
#pragma unroll
        for (int d = 0; d < DDIM; d += 4) {
            const uint4 q = *(const uint4*)&wtu[m * WPAD + d];
            const float v0 = __uint_as_float(q.x), v1 = __uint_as_float(q.y);
            const float v2 = __uint_as_float(q.z), v3 = __uint_as_float(q.w);
            acc += v0 * v0 + v1 * v1 + v2 * v2 + v3 * v3;
        }
        buf[m] = acc;
    }
    __syncthreads();
    float wsql[16];
#pragma unroll
    for (int j = 0; j < 16; j++) wsql[j] = buf[j * 32 + lane];

    float avg_acc[16];
#pragma unroll
    for (int j = 0; j < 16; j++) avg_acc[j] = 0.f;
    float kl_acc = 0.f;          // lane-uniform (built from reduced row scalars)

    for (int tile = blockIdx.x; tile < n_tiles; tile += gridDim.x) {
        const int b  = tile >> 7;
        const int t0 = (tile & 127) * TILE;

        __syncthreads();                        // prev tile fully consumed
        for (int i = tid; i < DDIM * TILE; i += NTHR) {
            const int d = i >> 5, t = i & 31;
            xsu[d * XSTR + t] = f2tf32(2.0f * x[((size_t)b * DDIM + d) * TDIM + t0 + t]);
        }
        __syncthreads();

        // ========== GEMM1 (mma.sync tf32): D[m][t] = w_m . 2x_t ==========
        uint32_t bf[4][16];
#pragma unroll
        for (int nt = 0; nt < 4; nt++)
#pragma unroll
            for (int k = 0; k < 8; k++) {
                bf[nt][k*2]   = xsu[(k*8 + tig)     * XSTR + nt*8 + g];
                bf[nt][k*2+1] = xsu[(k*8 + tig + 4) * XSTR + nt*8 + g];
            }
        float dre[4][4][4];
#pragma unroll
        for (int mt = 0; mt < 4; mt++)
#pragma unroll
            for (int nt = 0; nt < 4; nt++)
#pragma unroll
                for (int i = 0; i < 4; i++) dre[mt][nt][i] = 0.f;
#pragma unroll
        for (int mt = 0; mt < 4; mt++) {
            const uint32_t* wr0 = wtu + (mbase + mt*16 + g) * WPAD;
            const uint32_t* wr1 = wr0 + 8 * WPAD;
#pragma unroll
            for (int k = 0; k < 8; k++) {
                const uint32_t a0 = wr0[k*8 + tig];
                const uint32_t a1 = wr1[k*8 + tig];
                const uint32_t a2 = wr0[k*8 + tig + 4];
                const uint32_t a3 = wr1[k*8 + tig + 4];
#pragma unroll
                for (int nt = 0; nt < 4; nt++)
                    mma8(dre[mt][nt], a0, a1, a2, a3, bf[nt][k*2], bf[nt][k*2+1]);
            }
        }
#pragma unroll
        for (int mt = 0; mt < 4; mt++)
#pragma unroll
            for (int nt = 0; nt < 4; nt++) {
                const int tcol = nt*8 + 2*tig;
                const int m0 = mbase + mt*16 + g;
                buf[tcol * BSTR + m0]           = dre[mt][nt][0];
                buf[(tcol + 1) * BSTR + m0]     = dre[mt][nt][1];
                buf[tcol * BSTR + m0 + 8]       = dre[mt][nt][2];
                buf[(tcol + 1) * BSTR + m0 + 8] = dre[mt][nt][3];
            }

        // Prefetch ALL u for this warp's 4 rows (MLP=64) before the barrier.
        float uu[4][16];
        {
            const float* ub = u + (size_t)(b * TDIM + t0 + r0) * MDIM + lane;
#pragma unroll
            for (int r = 0; r < 4; r++)
#pragma unroll
                for (int j = 0; j < 16; j++)
                    uu[r][j] = ub[(size_t)r * MDIM + j*32];
        }
        __syncthreads();

        // ========== softmaxes, row-batched reductions (R13 structure) ==========
        float s[4][16];
#pragma unroll
        for (int r = 0; r < 4; r++)
#pragma unroll
            for (int j = 0; j < 16; j++)
                s[r][j] = buf[(r0 + r) * BSTR + j*32 + lane] - wsql[j];

        float mx[4];
#pragma unroll
        for (int r = 0; r < 4; r++) {
            mx[r] = s[r][0];
#pragma unroll
            for (int j = 1; j < 16; j++) mx[r] = fmaxf(mx[r], s[r][j]);
        }
#pragma unroll
        for (int m = 16; m > 0; m >>= 1)
#pragma unroll
            for (int r = 0; r < 4; r++)
                mx[r] = fmaxf(mx[r], __shfl_xor_sync(0xffffffffu, mx[r], m));

        // se = sum exp(s-mx); ses = sum exp(s-mx)*(s-mx)  (KL identity inputs)
        float se[4]  = {0.f, 0.f, 0.f, 0.f};
        float ses[4] = {0.f, 0.f, 0.f, 0.f};
#pragma unroll
        for (int r = 0; r < 4; r++)
#pragma unroll
            for (int j = 0; j < 16; j++) {
                const float d = s[r][j] - mx[r];
                const float e = __expf(d);
                se[r]  += e;
                ses[r] += e * d;
            }
#pragma unroll
        for (int m = 16; m > 0; m >>= 1)
#pragma unroll
            for (int r = 0; r < 4; r++) {
                se[r]  += __shfl_xor_sync(0xffffffffu, se[r],  m);
                ses[r] += __shfl_xor_sync(0xffffffffu, ses[r], m);
            }
#pragma unroll
        for (int r = 0; r < 4; r++) {
            const float lse = logf(se[r]);   // precise (MUFU bias breaks KL)
            // KL row = sum p*(lp + lnM) = ses/se - lse + lnM  (exact identity,
            // numerically validated at threshold in R14)
            kl_acc += __fdividef(ses[r], se[r]) - lse + LN_M;
        }

        // gumbel: overwrite s with y = 2(s + g)   (R13 body, unchanged)
#pragma unroll
        for (int r = 0; r < 4; r++)
#pragma unroll
            for (int j = 0; j < 16; j++) {
                const float v = fminf(fmaxf(uu[r][j], 1e-9f), 0.99999994f);
                const float gb = -__logf(-log_u(v));
                s[r][j] = 2.0f * (s[r][j] + gb);
            }
        float my[4];
#pragma unroll
        for (int r = 0; r < 4; r++) {
            my[r] = s[r][0];
#pragma unroll
            for (int j = 1; j < 16; j++) my[r] = fmaxf(my[r], s[r][j]);
        }
#pragma unroll
        for (int m = 16; m > 0; m >>= 1)
#pragma unroll
            for (int r = 0; r < 4; r++)
                my[r] = fmaxf(my[r], __shfl_xor_sync(0xffffffffu, my[r], m));

        float sy[4] = {0.f, 0.f, 0.f, 0.f};
#pragma unroll
        for (int r = 0; r < 4; r++)
#pragma unroll
            for (int j = 0; j < 16; j++) {
                s[r][j] = __expf(s[r][j] - my[r]);
                sy[r] += s[r][j];
            }
#pragma unroll
        for (int m = 16; m > 0; m >>= 1)
#pragma unroll
            for (int r = 0; r < 4; r++)
                sy[r] += __shfl_xor_sync(0xffffffffu, sy[r], m);

#pragma unroll
        for (int r = 0; r < 4; r++) {
            const float inv = 1.0f / sy[r];
#pragma unroll
            for (int j = 0; j < 16; j++) {
                const float p = s[r][j] * inv;
                avg_acc[j] += p;
                bufu[(r0 + r) * BSTR + j*32 + lane] = f2tf32(p);
            }
        }
        __syncthreads();

        // ========== GEMM2 (mma.sync tf32): out[t][d] = p . w ==========
        {
            const int tt0 = (warp & 1) * 16;
            const int dt0 = (warp >> 1) * 16;
            float dacc[2][4];
#pragma unroll
            for (int nt = 0; nt < 2; nt++)
#pragma unroll
                for (int i = 0; i < 4; i++) dacc[nt][i] = 0.f;
#pragma unroll 8
            for (int k0 = 0; k0 < MDIM; k0 += 8) {
                const uint32_t a0 = bufu[(tt0 + g)     * BSTR + k0 + tig];
                const uint32_t a1 = bufu[(tt0 + g + 8) * BSTR + k0 + tig];
                const uint32_t a2 = bufu[(tt0 + g)     * BSTR + k0 + tig + 4];
                const uint32_t a3 = bufu[(tt0 + g + 8) * BSTR + k0 + tig + 4];
#pragma unroll
                for (int nt = 0; nt < 2; nt++) {
                    const uint32_t b0 = wtu[(k0 + tig)     * WPAD + dt0 + nt*8 + g];
                    const uint32_t b1 = wtu[(k0 + tig + 4) * WPAD + dt0 + nt*8 + g];
                    mma8(dacc[nt], a0, a1, a2, a3, b0, b1);
                }
            }
            float* ob = out + (size_t)(b * TDIM + t0 + tt0) * DDIM;
#pragma unroll
            for (int nt = 0; nt < 2; nt++) {
                const int d0 = dt0 + nt*8 + 2*tig;
                *(float2*)&ob[(size_t)g * DDIM + d0]       = make_float2(dacc[nt][0], dacc[nt][1]);
                *(float2*)&ob[(size_t)(g + 8) * DDIM + d0] = make_float2(dacc[nt][2], dacc[nt][3]);
            }
        }
    }

    // ---- epilogue: CTA reduce in buf, then global atomics ----
    __syncthreads();
    for (int i = tid; i < MDIM; i += NTHR) buf[i] = 0.f;
    __syncthreads();
#pragma unroll
    for (int j = 0; j < 16; j++) atomicAdd(&buf[j*32 + lane], avg_acc[j]);
    __syncthreads();
    for (int i = tid; i < MDIM; i += NTHR) atomicAdd(&g_avg[i], buf[i]);
    // kl_acc is lane-uniform: one lane per warp adds it
    if (lane == 0) atomicAdd(&g_kl, kl_acc);
}

__global__ void vq_finalize_kernel(float* __restrict__ out, long long q, int B,
                                   float invN, long long out_size)
{
    __shared__ float red[16];
    const int tid = threadIdx.x, lane = tid & 31, warp = tid >> 5;
    const float a = g_avg[tid] * invN;
    float v = a * logf(a + 1e-10f);
    v = warp_sum(v);
    if (lane == 0) red[warp] = v;
    __syncthreads();
    if (tid == 0) {
        float t = 0.f;
#pragma unroll
        for (int i = 0; i < 16; i++) t += red[i];
        if (q < out_size)     out[q]     = g_kl / (float)B;
        if (q + 1 < out_size) out[q + 1] = expf(-t);
    }
}

extern "C" void kernel_launch(void* const* d_in, const int* in_sizes, int n_in,
                              void* d_out, int out_size)
{
    const float* x = (const float*)d_in[0];
    const float* u = (const float*)d_in[1];
    const float* w = (const float*)d_in[2];
    float* out = (float*)d_out;

    const int B = in_sizes[0] / (DDIM * TDIM);
    const int n_tiles = B * (TDIM / TILE);
    const long long q = (long long)B * TDIM * DDIM;

    const size_t smem_bytes = SMEM_FLOATS * sizeof(float);
    cudaFuncSetAttribute(vq_main_kernel,
                         cudaFuncAttributeMaxDynamicSharedMemorySize, (int)smem_bytes);
    const int grid = (n_tiles < NSM) ? n_tiles : NSM;

    vq_zero_kernel<<<1, 512>>>();
    vq_main_kernel<<<grid, NTHR, smem_bytes>>>(x, u, w, out, n_tiles);
    vq_finalize_kernel<<<1, 512>>>(out, q, B,
                                   1.0f / (float)((long long)B * TDIM),
                                   (long long)out_size);
    vq_zero_kernel<<<1, 512>>>();
}

// round 17
// speedup vs baseline: 1.3737x; 1.1897x over previous
#include <cuda_runtime.h>
#include <math.h>
#include <stdint.h>

#define TDIM 4096
#define MDIM 512
#define DDIM 64
#define WPAD 68
#define XSTR 40
#define BSTR 516
#define TILE 32
#define NTHR 256
#define NSM  152
#define LN_M 6.2383246250395075f

#define OFF_W   0                       // W tf32 [512][68] = 34816 words
#define OFF_X   34816                   // X tf32 [64][40]  = 2560
#define OFF_BUF 37376                   // buf [32][516]    = 16512
#define SMEM_FLOATS (OFF_BUF + 16512)

__device__ float g_avg[MDIM];
__device__ float g_kl;

static __device__ __forceinline__ uint32_t f2tf32(float v) {
    uint32_t b; asm("cvt.rna.tf32.f32 %0, %1;" : "=r"(b) : "f"(v)); return b;
}
static __device__ __forceinline__ void mma8(float d[4], uint32_t a0, uint32_t a1,
                                            uint32_t a2, uint32_t a3,
                                            uint32_t b0, uint32_t b1) {
    asm volatile("mma.sync.aligned.m16n8k8.row.col.f32.tf32.tf32.f32 "
                 "{%0,%1,%2,%3},{%4,%5,%6,%7},{%8,%9},{%0,%1,%2,%3};"
                 : "+f"(d[0]), "+f"(d[1]), "+f"(d[2]), "+f"(d[3])
                 : "r"(a0), "r"(a1), "r"(a2), "r"(a3), "r"(b0), "r"(b1));
}
// log(u), u in [1e-9,1): MUFU away from 1, 3-term Taylor near 1 (validated)
static __device__ __forceinline__ float log_u(float uu) {
    const float t = uu - 1.0f;
    const float near1 = t * fmaf(t, fmaf(t, 0.33333333f, -0.5f), 1.0f);
    return (uu > 0.999f) ? near1 : __logf(uu);
}
static __device__ __forceinline__ float warp_sum(float v) {
#pragma unroll
    for (int m = 16; m > 0; m >>= 1) v += __shfl_xor_sync(0xffffffffu, v, m);
    return v;
}

__global__ void vq_zero_kernel() {
    if (threadIdx.x < MDIM) g_avg[threadIdx.x] = 0.f;
    if (threadIdx.x == 0) g_kl = 0.f;
}

__global__ void __launch_bounds__(NTHR, 1)
vq_main_kernel(const float* __restrict__ x, const float* __restrict__ u,
               const float* __restrict__ w, float* __restrict__ out, int n_tiles)
{
    extern __shared__ float sm[];
    uint32_t* wtu = (uint32_t*)(sm + OFF_W);     // tf32 W, [m][WPAD]
    uint32_t* xsu = (uint32_t*)(sm + OFF_X);     // tf32 X, [d][XSTR]
    float*    buf = sm + OFF_BUF;                // logits then tf32 samples
    uint32_t* bufu = (uint32_t*)buf;

    const int tid = threadIdx.x, lane = tid & 31, warp = tid >> 5;
    const int r0 = warp * 4;
    const int g = lane >> 2, tig = lane & 3;
    const int mbase = warp * 64;

    // ---- stage W once as tf32 (rounded: unbiased) ----
    for (int i = tid; i < MDIM * DDIM; i += NTHR)
        wtu[(i >> 6) * WPAD + (i & 63)] = f2tf32(w[i]);
    __syncthreads();
    // ---- wsq from the tf32 codebook ----
    for (int m = tid; m < MDIM; m += NTHR) {
        float acc = 0.f;
#pragma unroll
        for (int d = 0; d < DDIM; d += 4) {
            const uint4 q = *(const uint4*)&wtu[m * WPAD + d];
            const float v0 = __uint_as_float(q.x), v1 = __uint_as_float(q.y);
            const float v2 = __uint_as_float(q.z), v3 = __uint_as_float(q.w);
            acc += v0 * v0 + v1 * v1 + v2 * v2 + v3 * v3;
        }
        buf[m] = acc;
    }
    __syncthreads();
    float wsql[16];
#pragma unroll
    for (int j = 0; j < 16; j++) wsql[j] = buf[j * 32 + lane];

    float avg_acc[16];
#pragma unroll
    for (int j = 0; j < 16; j++) avg_acc[j] = 0.f;
    float kl_acc = 0.f;          // lane-uniform (built from reduced row scalars)

    // ---- peel: stage x for this CTA's first tile ----
    if (blockIdx.x < n_tiles) {
        const int b0 = blockIdx.x >> 7, t00 = (blockIdx.x & 127) * TILE;
        for (int i = tid; i < DDIM * TILE; i += NTHR) {
            const int d = i >> 5, t = i & 31;
            xsu[d * XSTR + t] = f2tf32(2.0f * x[((size_t)b0 * DDIM + d) * TDIM + t00 + t]);
        }
    }
    __syncthreads();

    for (int tile = blockIdx.x; tile < n_tiles; tile += gridDim.x) {
        const int b  = tile >> 7;
        const int t0 = (tile & 127) * TILE;

        __syncthreads();          // C: prev GEMM2 done reading buf (no-op first iter)

        // ========== GEMM1 (mma.sync tf32): D[m][t] = w_m . 2x_t ==========
        uint32_t bf[4][16];
#pragma unroll
        for (int nt = 0; nt < 4; nt++)
#pragma unroll
            for (int k = 0; k < 8; k++) {
                bf[nt][k*2]   = xsu[(k*8 + tig)     * XSTR + nt*8 + g];
                bf[nt][k*2+1] = xsu[(k*8 + tig + 4) * XSTR + nt*8 + g];
            }
        float dre[4][4][4];
#pragma unroll
        for (int mt = 0; mt < 4; mt++)
#pragma unroll
            for (int nt = 0; nt < 4; nt++)
#pragma unroll
                for (int i = 0; i < 4; i++) dre[mt][nt][i] = 0.f;
#pragma unroll
        for (int mt = 0; mt < 4; mt++) {
            const uint32_t* wr0 = wtu + (mbase + mt*16 + g) * WPAD;
            const uint32_t* wr1 = wr0 + 8 * WPAD;
#pragma unroll
            for (int k = 0; k < 8; k++) {
                const uint32_t a0 = wr0[k*8 + tig];
                const uint32_t a1 = wr1[k*8 + tig];
                const uint32_t a2 = wr0[k*8 + tig + 4];
                const uint32_t a3 = wr1[k*8 + tig + 4];
#pragma unroll
                for (int nt = 0; nt < 4; nt++)
                    mma8(dre[mt][nt], a0, a1, a2, a3, bf[nt][k*2], bf[nt][k*2+1]);
            }
        }
#pragma unroll
        for (int mt = 0; mt < 4; mt++)
#pragma unroll
            for (int nt = 0; nt < 4; nt++) {
                const int tcol = nt*8 + 2*tig;
                const int m0 = mbase + mt*16 + g;
                buf[tcol * BSTR + m0]           = dre[mt][nt][0];
                buf[(tcol + 1) * BSTR + m0]     = dre[mt][nt][1];
                buf[tcol * BSTR + m0 + 8]       = dre[mt][nt][2];
                buf[(tcol + 1) * BSTR + m0 + 8] = dre[mt][nt][3];
            }

        // Prefetch u (this tile, MLP=64) and next tile's x (MLP=8): latency
        // hides under sync A + softmax.
        float uu[4][16];
        {
            const float* ub = u + (size_t)(b * TDIM + t0 + r0) * MDIM + lane;
#pragma unroll
            for (int r = 0; r < 4; r++)
#pragma unroll
                for (int j = 0; j < 16; j++)
                    uu[r][j] = ub[(size_t)r * MDIM + j*32];
        }
        float xpre[8];
        const int nxt = tile + gridDim.x;
        if (nxt < n_tiles) {
            const int nb = nxt >> 7, nt0 = (nxt & 127) * TILE;
#pragma unroll
            for (int q2 = 0; q2 < 8; q2++) {
                const int i = tid + q2 * NTHR;
                xpre[q2] = 2.0f * x[((size_t)nb * DDIM + (i >> 5)) * TDIM + nt0 + (i & 31)];
            }
        }
        __syncthreads();          // A: scatter complete; all bf loads done -> xsu free

        // stage next tile's x from registers (covered by softmax below)
        if (nxt < n_tiles) {
#pragma unroll
            for (int q2 = 0; q2 < 8; q2++) {
                const int i = tid + q2 * NTHR;
                xsu[(i >> 5) * XSTR + (i & 31)] = f2tf32(xpre[q2]);
            }
        }

        // ========== softmaxes (separated passes; e reused for gumbel) ==========
        float s[4][16];
#pragma unroll
        for (int r = 0; r < 4; r++)
#pragma unroll
            for (int j = 0; j < 16; j++)
                s[r][j] = buf[(r0 + r) * BSTR + j*32 + lane] - wsql[j];

        float mx[4];
#pragma unroll
        for (int r = 0; r < 4; r++) {
            mx[r] = s[r][0];
#pragma unroll
            for (int j = 1; j < 16; j++) mx[r] = fmaxf(mx[r], s[r][j]);
        }
#pragma unroll
        for (int m = 16; m > 0; m >>= 1)
#pragma unroll
            for (int r = 0; r < 4; r++)
                mx[r] = fmaxf(mx[r], __shfl_xor_sync(0xffffffffu, mx[r], m));

        // pass B: e = exp(s-mx) stored in-place; se, ses for the KL identity
        float se[4]  = {0.f, 0.f, 0.f, 0.f};
        float ses[4] = {0.f, 0.f, 0.f, 0.f};
#pragma unroll
        for (int r = 0; r < 4; r++)
#pragma unroll
            for (int j = 0; j < 16; j++) {
                const float d = s[r][j] - mx[r];
                const float e = __expf(d);
                se[r]  += e;
                ses[r] += e * d;
                s[r][j] = e;
            }
#pragma unroll
        for (int m = 16; m > 0; m >>= 1)
#pragma unroll
            for (int r = 0; r < 4; r++) {
                se[r]  += __shfl_xor_sync(0xffffffffu, se[r],  m);
                ses[r] += __shfl_xor_sync(0xffffffffu, ses[r], m);
            }
#pragma unroll
        for (int r = 0; r < 4; r++) {
            const float lse = logf(se[r]);   // precise (MUFU bias breaks KL)
            kl_acc += __fdividef(ses[r], se[r]) - lse + LN_M;
        }

        // pass C: gumbel sample weight val = (e / log u)^2  (R14-validated
        // identity; exp(-2mx) factor cancels in normalization). Bounded:
        // |log u| >= 6e-8 -> val <= 5e15, sy <= 8e16 << fp32 max.
        float sy[4] = {0.f, 0.f, 0.f, 0.f};
#pragma unroll
        for (int r = 0; r < 4; r++)
#pragma unroll
            for (int j = 0; j < 16; j++) {
                const float v = fminf(fmaxf(uu[r][j], 1e-9f), 0.99999994f);
                const float t = __fdividef(s[r][j], log_u(v));
                const float val = t * t;
                s[r][j] = val;
                sy[r] += val;
            }
#pragma unroll
        for (int m = 16; m > 0; m >>= 1)
#pragma unroll
            for (int r = 0; r < 4; r++)
                sy[r] += __shfl_xor_sync(0xffffffffu, sy[r], m);

#pragma unroll
        for (int r = 0; r < 4; r++) {
            const float inv = 1.0f / sy[r];
#pragma unroll
            for (int j = 0; j < 16; j++) {
                const float p = s[r][j] * inv;
                avg_acc[j] += p;
                bufu[(r0 + r) * BSTR + j*32 + lane] = f2tf32(p);
            }
        }
        __syncthreads();          // B: samples visible

        // ========== GEMM2 (mma.sync tf32): out[t][d] = p . w ==========
        {
            const int tt0 = (warp & 1) * 16;
            const int dt0 = (warp >> 1) * 16;
            float dacc[2][4];
#pragma unroll
            for (int nt = 0; nt < 2; nt++)
#pragma unroll
                for (int i = 0; i < 4; i++) dacc[nt][i] = 0.f;
#pragma unroll 8
            for (int k0 = 0; k0 < MDIM; k0 += 8) {
                const uint32_t a0 = bufu[(tt0 + g)     * BSTR + k0 + tig];
                const uint32_t a1 = bufu[(tt0 + g + 8) * BSTR + k0 + tig];
                const uint32_t a2 = bufu[(tt0 + g)     * BSTR + k0 + tig + 4];
                const uint32_t a3 = bufu[(tt0 + g + 8) * BSTR + k0 + tig + 4];
#pragma unroll
                for (int nt = 0; nt < 2; nt++) {
                    const uint32_t b0 = wtu[(k0 + tig)     * WPAD + dt0 + nt*8 + g];
                    const uint32_t b1 = wtu[(k0 + tig + 4) * WPAD + dt0 + nt*8 + g];
                    mma8(dacc[nt], a0, a1, a2, a3, b0, b1);
                }
            }
            float* ob = out + (size_t)(b * TDIM + t0 + tt0) * DDIM;
#pragma unroll
            for (int nt = 0; nt < 2; nt++) {
                const int d0 = dt0 + nt*8 + 2*tig;
                *(float2*)&ob[(size_t)g * DDIM + d0]       = make_float2(dacc[nt][0], dacc[nt][1]);
                *(float2*)&ob[(size_t)(g + 8) * DDIM + d0] = make_float2(dacc[nt][2], dacc[nt][3]);
            }
        }
    }

    // ---- epilogue: CTA reduce in buf, then global atomics ----
    __syncthreads();
    for (int i = tid; i < MDIM; i += NTHR) buf[i] = 0.f;
    __syncthreads();
#pragma unroll
    for (int j = 0; j < 16; j++) atomicAdd(&buf[j*32 + lane], avg_acc[j]);
    __syncthreads();
    for (int i = tid; i < MDIM; i += NTHR) atomicAdd(&g_avg[i], buf[i]);
    if (lane == 0) atomicAdd(&g_kl, kl_acc);
}

__global__ void vq_finalize_kernel(float* __restrict__ out, long long q, int B,
                                   float invN, long long out_size)
{
    __shared__ float red[16];
    const int tid = threadIdx.x, lane = tid & 31, warp = tid >> 5;
    const float a = g_avg[tid] * invN;
    float v = a * logf(a + 1e-10f);
    v = warp_sum(v);
    if (lane == 0) red[warp] = v;
    __syncthreads();
    if (tid == 0) {
        float t = 0.f;
#pragma unroll
        for (int i = 0; i < 16; i++) t += red[i];
        if (q < out_size)     out[q]     = g_kl / (float)B;
        if (q + 1 < out_size) out[q + 1] = expf(-t);
    }
}

extern "C" void kernel_launch(void* const* d_in, const int* in_sizes, int n_in,
                              void* d_out, int out_size)
{
    const float* x = (const float*)d_in[0];
    const float* u = (const float*)d_in[1];
    const float* w = (const float*)d_in[2];
    float* out = (float*)d_out;

    const int B = in_sizes[0] / (DDIM * TDIM);
    const int n_tiles = B * (TDIM / TILE);
    const long long q = (long long)B * TDIM * DDIM;

    const size_t smem_bytes = SMEM_FLOATS * sizeof(float);
    cudaFuncSetAttribute(vq_main_kernel,
                         cudaFuncAttributeMaxDynamicSharedMemorySize, (int)smem_bytes);
    const int grid = (n_tiles < NSM) ? n_tiles : NSM;

    vq_zero_kernel<<<1, 512>>>();
    vq_main_kernel<<<grid, NTHR, smem_bytes>>>(x, u, w, out, n_tiles);
    vq_finalize_kernel<<<1, 512>>>(out, q, B,
                                   1.0f / (float)((long long)B * TDIM),
                                   (long long)out_size);
    vq_zero_kernel<<<1, 512>>>();
}